// round 2
// baseline (speedup 1.0000x reference)
#include <cuda_runtime.h>
#include <cuda_bf16.h>

#define NN 4096
#define HH 4

// ---------------- scratch (device globals; no allocation allowed) ----------------
__device__ float    g_h1 [NN * 512];   // x @ W1              [n][h*128+f]
__device__ float    g_x1 [NN * 512];   // gat1 out            [n][h*128+f]
__device__ float    g_y1 [NN * 64];    // x1 @ lw1 + lb1
__device__ float    g_x2 [NN * 64];    // bn_elu(y1)
__device__ float    g_h2 [NN * 128];   // x2 @ W2             [n][h*32+f]
__device__ float    g_x3 [NN * 128];   // gat2 out
__device__ float    g_y2 [NN * 16];    // x3 @ lw2 + lb2
__device__ float    g_es1[HH * NN];
__device__ float    g_ed1[HH * NN];
__device__ float    g_es2[HH * NN];
__device__ float    g_ed2[HH * NN];
__device__ unsigned g_adjbits[NN * (NN / 32)];  // 2 MB bitmask (L2-resident)
__device__ float    g_stats[256];               // [0..127] mean, [128..255] rstd

// ---------------- adjacency packing: int32 [N,N] -> bitmask ----------------
__global__ void pack_adj_k(const int* __restrict__ adj, unsigned* __restrict__ bits) {
    int gid = blockIdx.x * blockDim.x + threadIdx.x;   // over NN*NN
    unsigned pred = adj[gid] > 0 ? 1u : 0u;
    unsigned word = __ballot_sync(0xffffffffu, pred);
    if ((threadIdx.x & 31) == 0) bits[gid >> 5] = word;
}

// ---------------- generic fp32 tiled GEMM (+optional bias) ----------------
// C[M,N] = A[M,K] @ B[K,N] (+ bias[N]); (BM/TM)*(BN/TN)==256 threads.
template<int BM, int BN, int BK, int TM, int TN>
__global__ void gemm_k(const float* __restrict__ A, const float* __restrict__ B,
                       const float* __restrict__ bias, float* __restrict__ C,
                       int M, int N, int K) {
    __shared__ float As[BK][BM];
    __shared__ float Bs[BK][BN];
    constexpr int TX = BN / TN;
    int tid = threadIdx.x;
    int tx = tid % TX, ty = tid / TX;
    int m0 = blockIdx.y * BM, n0 = blockIdx.x * BN;
    float acc[TM][TN];
#pragma unroll
    for (int i = 0; i < TM; i++)
#pragma unroll
        for (int j = 0; j < TN; j++) acc[i][j] = 0.f;

    for (int k0 = 0; k0 < K; k0 += BK) {
#pragma unroll
        for (int idx = tid; idx < BM * BK; idx += 256) {
            int m = idx / BK, k = idx % BK;
            As[k][m] = A[(m0 + m) * K + k0 + k];
        }
#pragma unroll
        for (int idx = tid; idx < BK * BN; idx += 256) {
            int k = idx / BN, n = idx % BN;
            Bs[k][n] = B[(k0 + k) * N + n0 + n];
        }
        __syncthreads();
#pragma unroll
        for (int k = 0; k < BK; k++) {
            float ra[TM], rb[TN];
#pragma unroll
            for (int i = 0; i < TM; i++) ra[i] = As[k][ty * TM + i];
#pragma unroll
            for (int j = 0; j < TN; j++) rb[j] = Bs[k][tx * TN + j];
#pragma unroll
            for (int i = 0; i < TM; i++)
#pragma unroll
                for (int j = 0; j < TN; j++) acc[i][j] = fmaf(ra[i], rb[j], acc[i][j]);
        }
        __syncthreads();
    }
#pragma unroll
    for (int i = 0; i < TM; i++)
#pragma unroll
        for (int j = 0; j < TN; j++) {
            float v = acc[i][j];
            if (bias) v += bias[n0 + tx * TN + j];
            C[(m0 + ty * TM + i) * N + n0 + tx * TN + j] = v;
        }
}

// ---------------- es / ed per-node attention logits ----------------
template<int F>
__global__ void esed_k(const float* __restrict__ h, const float* __restrict__ asv,
                       const float* __restrict__ adv, float* __restrict__ es,
                       float* __restrict__ ed) {
    int n = blockIdx.x;
    int t = threadIdx.x;  // 128 threads
    __shared__ float rs[128], rd[128];
    for (int hd = 0; hd < HH; hd++) {
        float vs = 0.f, vd = 0.f;
        for (int f = t; f < F; f += 128) {
            float hv = h[n * (HH * F) + hd * F + f];
            vs = fmaf(hv, asv[hd * F + f], vs);
            vd = fmaf(hv, adv[hd * F + f], vd);
        }
        rs[t] = vs; rd[t] = vd;
        __syncthreads();
#pragma unroll
        for (int s = 64; s > 0; s >>= 1) {
            if (t < s) { rs[t] += rs[t + s]; rd[t] += rd[t + s]; }
            __syncthreads();
        }
        if (t == 0) { es[hd * NN + n] = rs[0]; ed[hd * NN + n] = rd[0]; }
        __syncthreads();
    }
}

// ---------------- fused masked-softmax attention aggregation ----------------
// out[i, head*F + f] = sum_j adj_ij * exp(lrelu(es_i+ed_j)) * h[j, head*F+f] / den_i
// Flash-style: never materializes the [N,N] attention matrix.
template<int F, int ROWS, int JT>
__global__ void attn_k(const float* __restrict__ h, const float* __restrict__ es,
                       const float* __restrict__ ed, const unsigned* __restrict__ bits,
                       float* __restrict__ out) {
    constexpr int FV  = F / 4;        // float4 slots per row
    constexpr int TY  = 256 / FV;     // thread rows in FMA layout
    constexpr int RPT = ROWS / TY;    // rows per thread
    constexpr int CPR = 256 / ROWS;   // threads per row (weight phase)
    constexpr int JPT = JT / CPR;     // j's per thread (weight phase)
    constexpr int HF  = HH * F;
    constexpr int WSS = 68;           // padded ws row stride (16B aligned, conflict-free)

    __shared__ float4 hs[JT * FV];
    __shared__ float  ws[ROWS][WSS];
    __shared__ float  dens[ROWS];

    int t = threadIdx.x;
    int head = blockIdx.y;
    int i0 = blockIdx.x * ROWS;
    int tx = t % FV, ty = t / FV;     // FMA layout
    int wr = t / CPR, wc = t % CPR;   // weight layout

    float es_i = es[head * NN + i0 + wr];

    float4 acc[RPT];
#pragma unroll
    for (int r = 0; r < RPT; r++) acc[r] = make_float4(0.f, 0.f, 0.f, 0.f);
    if (t < ROWS) dens[t] = 0.f;
    __syncthreads();

    for (int j0 = 0; j0 < NN; j0 += JT) {
        // --- load h tile + compute weights (disjoint shared targets) ---
#pragma unroll
        for (int k = 0; k < (JT * FV) / 256; k++) {
            int idx = t + k * 256;
            int jj = idx / FV, v = idx % FV;
            hs[idx] = reinterpret_cast<const float4*>(h + (j0 + jj) * HF + head * F)[v];
        }
        unsigned word = bits[(i0 + wr) * (NN / 32) + ((j0 + wc * JPT) >> 5)];
        int bit0 = (wc * JPT) & 31;
        float part = 0.f;
#pragma unroll
        for (int q = 0; q < JPT; q++) {
            int jj = wc * JPT + q;
            float z = es_i + ed[head * NN + j0 + jj];
            z = z > 0.f ? z : 0.2f * z;
            float w = ((word >> (bit0 + q)) & 1u) ? __expf(z) : 0.f;
            ws[wr][jj] = w;
            part += w;
        }
#pragma unroll
        for (int off = CPR / 2; off > 0; off >>= 1)
            part += __shfl_down_sync(0xffffffffu, part, off, CPR);
        if (wc == 0) dens[wr] += part;
        __syncthreads();

        // --- FMA phase: acc += w * h ---
#pragma unroll 2
        for (int jq = 0; jq < JT / 4; jq++) {
            float wa[RPT][4];
#pragma unroll
            for (int r = 0; r < RPT; r++) {
                float4 wv = reinterpret_cast<const float4*>(ws[ty + r * TY])[jq];
                wa[r][0] = wv.x; wa[r][1] = wv.y; wa[r][2] = wv.z; wa[r][3] = wv.w;
            }
#pragma unroll
            for (int q = 0; q < 4; q++) {
                float4 hv = hs[(jq * 4 + q) * FV + tx];
#pragma unroll
                for (int r = 0; r < RPT; r++) {
                    acc[r].x = fmaf(wa[r][q], hv.x, acc[r].x);
                    acc[r].y = fmaf(wa[r][q], hv.y, acc[r].y);
                    acc[r].z = fmaf(wa[r][q], hv.z, acc[r].z);
                    acc[r].w = fmaf(wa[r][q], hv.w, acc[r].w);
                }
            }
        }
        __syncthreads();
    }

#pragma unroll
    for (int r = 0; r < RPT; r++) {
        int row = ty + r * TY;
        float inv = 1.f / dens[row];
        float4 o = make_float4(acc[r].x * inv, acc[r].y * inv, acc[r].z * inv, acc[r].w * inv);
        reinterpret_cast<float4*>(out + (i0 + row) * HF + head * F)[tx] = o;
    }
}

// ---------------- batchnorm stats (biased var, per column) ----------------
template<int C>
__global__ void bnstats_k(const float* __restrict__ y, float* __restrict__ stats) {
    int c = blockIdx.x;
    int t = threadIdx.x;  // 256
    float s = 0.f, q = 0.f;
    for (int r = t; r < NN; r += 256) {
        float v = y[r * C + c];
        s += v; q = fmaf(v, v, q);
    }
    __shared__ float ss[256], qq[256];
    ss[t] = s; qq[t] = q;
    __syncthreads();
#pragma unroll
    for (int o = 128; o > 0; o >>= 1) {
        if (t < o) { ss[t] += ss[t + o]; qq[t] += qq[t + o]; }
        __syncthreads();
    }
    if (t == 0) {
        float mean = ss[0] / (float)NN;
        float var  = qq[0] / (float)NN - mean * mean;
        stats[c]       = mean;
        stats[128 + c] = rsqrtf(var + 1e-5f);
    }
}

// ---------------- normalize + affine + ELU ----------------
template<int C>
__global__ void bnelu_k(const float* __restrict__ y, const float* __restrict__ stats,
                        const float* __restrict__ g, const float* __restrict__ b,
                        float* __restrict__ out) {
    int idx = blockIdx.x * blockDim.x + threadIdx.x;
    if (idx >= NN * C) return;
    int c = idx % C;
    float v = (y[idx] - stats[c]) * stats[128 + c];
    v = fmaf(v, g[c], b[c]);
    out[idx] = v > 0.f ? v : expm1f(v);
}

// ---------------- launch ----------------
extern "C" void kernel_launch(void* const* d_in, const int* in_sizes, int n_in,
                              void* d_out, int out_size) {
    const float* x   = (const float*)d_in[0];
    const int*   adj = (const int*)d_in[1];
    const float* W1  = (const float*)d_in[2];
    const float* a1s = (const float*)d_in[3];
    const float* a1d = (const float*)d_in[4];
    const float* lw1 = (const float*)d_in[5];
    const float* lb1 = (const float*)d_in[6];
    const float* g1  = (const float*)d_in[7];
    const float* be1 = (const float*)d_in[8];
    const float* W2  = (const float*)d_in[9];
    const float* a2s = (const float*)d_in[10];
    const float* a2d = (const float*)d_in[11];
    const float* lw2 = (const float*)d_in[12];
    const float* lb2 = (const float*)d_in[13];
    const float* g2  = (const float*)d_in[14];
    const float* be2 = (const float*)d_in[15];
    float* out = (float*)d_out;

    // Resolve scratch addresses every call (deterministic, non-enqueuing,
    // graph-capture-safe; no static guards per harness rules).
    float *h1, *x1, *y1, *x2, *h2, *x3, *y2, *es1, *ed1, *es2, *ed2, *stats;
    unsigned* bitsp;
    cudaGetSymbolAddress((void**)&h1,  g_h1);
    cudaGetSymbolAddress((void**)&x1,  g_x1);
    cudaGetSymbolAddress((void**)&y1,  g_y1);
    cudaGetSymbolAddress((void**)&x2,  g_x2);
    cudaGetSymbolAddress((void**)&h2,  g_h2);
    cudaGetSymbolAddress((void**)&x3,  g_x3);
    cudaGetSymbolAddress((void**)&y2,  g_y2);
    cudaGetSymbolAddress((void**)&es1, g_es1);
    cudaGetSymbolAddress((void**)&ed1, g_ed1);
    cudaGetSymbolAddress((void**)&es2, g_es2);
    cudaGetSymbolAddress((void**)&ed2, g_ed2);
    cudaGetSymbolAddress((void**)&stats, g_stats);
    cudaGetSymbolAddress((void**)&bitsp, g_adjbits);

    // pack adjacency to bits (67MB -> 2MB, read once)
    pack_adj_k<<<(NN * NN) / 256, 256>>>(adj, bitsp);

    // ---- layer 1 GAT ----
    gemm_k<64, 64, 16, 4, 4><<<dim3(512 / 64, NN / 64), 256>>>(x, W1, nullptr, h1, NN, 512, 512);
    esed_k<128><<<NN, 128>>>(h1, a1s, a1d, es1, ed1);
    attn_k<128, 32, 64><<<dim3(NN / 32, HH), 256>>>(h1, es1, ed1, bitsp, x1);

    // ---- MLP 1 + BN + ELU ----
    gemm_k<64, 64, 16, 4, 4><<<dim3(1, NN / 64), 256>>>(x1, lw1, lb1, y1, NN, 64, 512);
    bnstats_k<64><<<64, 256>>>(y1, stats);
    bnelu_k<64><<<(NN * 64) / 256, 256>>>(y1, stats, g1, be1, x2);

    // ---- layer 2 GAT ----
    gemm_k<64, 64, 16, 4, 4><<<dim3(2, NN / 64), 256>>>(x2, W2, nullptr, h2, NN, 128, 64);
    esed_k<32><<<NN, 128>>>(h2, a2s, a2d, es2, ed2);
    attn_k<32, 32, 64><<<dim3(NN / 32, HH), 256>>>(h2, es2, ed2, bitsp, x3);

    // ---- MLP 2 + BN + ELU ----
    gemm_k<64, 16, 16, 4, 1><<<dim3(1, NN / 64), 256>>>(x3, lw2, lb2, y2, NN, 16, 128);
    bnstats_k<16><<<16, 256>>>(y2, stats);
    bnelu_k<16><<<(NN * 16) / 256, 256>>>(y2, stats, g2, be2, out);
}

// round 5
// speedup vs baseline: 1.6651x; 1.6651x over previous
#include <cuda_runtime.h>
#include <cuda_bf16.h>
#include <cstdint>

#define NN 4096
#define HH 4

// ---------------- scratch (device globals; no allocation allowed) ----------------
__device__ float  g_h1 [NN * 512];
__device__ float  g_x1 [NN * 512];
__device__ float  g_y1 [NN * 64];
__device__ float  g_x2 [NN * 64];
__device__ float  g_h2 [NN * 128];
__device__ float  g_x3 [NN * 128];
__device__ float  g_y2 [NN * 16];
__device__ float4 g_rowc1[HH * NN];   // {es, e^es, e^{0.2es}, 0}
__device__ float4 g_evq1 [HH * NN];   // {ed, e^ed, e^{0.2ed}, 0}
__device__ float4 g_rowc2[HH * NN];
__device__ float4 g_evq2 [HH * NN];
__device__ unsigned g_adjbits[NN * (NN / 32)];
__device__ float  g_stats[256];

// ---------------- adjacency packing ----------------
__global__ void pack_adj_k(const int* __restrict__ adj, unsigned* __restrict__ bits) {
    int gid = blockIdx.x * blockDim.x + threadIdx.x;
    unsigned pred = adj[gid] > 0 ? 1u : 0u;
    unsigned word = __ballot_sync(0xffffffffu, pred);
    if ((threadIdx.x & 31) == 0) bits[gid >> 5] = word;
}

// ---------------- generic fp32 tiled GEMM (+optional bias) ----------------
template<int BM, int BN, int BK, int TM, int TN>
__global__ void gemm_k(const float* __restrict__ A, const float* __restrict__ B,
                       const float* __restrict__ bias, float* __restrict__ C,
                       int M, int N, int K) {
    __shared__ float As[BK][BM];
    __shared__ float Bs[BK][BN];
    constexpr int TX = BN / TN;
    int tid = threadIdx.x;
    int tx = tid % TX, ty = tid / TX;
    int m0 = blockIdx.y * BM, n0 = blockIdx.x * BN;
    float acc[TM][TN];
#pragma unroll
    for (int i = 0; i < TM; i++)
#pragma unroll
        for (int j = 0; j < TN; j++) acc[i][j] = 0.f;

    for (int k0 = 0; k0 < K; k0 += BK) {
#pragma unroll
        for (int idx = tid; idx < BM * BK; idx += 256) {
            int m = idx / BK, k = idx % BK;
            As[k][m] = A[(m0 + m) * K + k0 + k];
        }
#pragma unroll
        for (int idx = tid; idx < BK * BN; idx += 256) {
            int k = idx / BN, n = idx % BN;
            Bs[k][n] = B[(k0 + k) * N + n0 + n];
        }
        __syncthreads();
#pragma unroll
        for (int k = 0; k < BK; k++) {
            float ra[TM], rb[TN];
#pragma unroll
            for (int i = 0; i < TM; i++) ra[i] = As[k][ty * TM + i];
#pragma unroll
            for (int j = 0; j < TN; j++) rb[j] = Bs[k][tx * TN + j];
#pragma unroll
            for (int i = 0; i < TM; i++)
#pragma unroll
                for (int j = 0; j < TN; j++) acc[i][j] = fmaf(ra[i], rb[j], acc[i][j]);
        }
        __syncthreads();
    }
#pragma unroll
    for (int i = 0; i < TM; i++)
#pragma unroll
        for (int j = 0; j < TN; j++) {
            float v = acc[i][j];
            if (bias) v += bias[n0 + tx * TN + j];
            C[(m0 + ty * TM + i) * N + n0 + tx * TN + j] = v;
        }
}

// ---------------- per-node logits + factorized exponentials ----------------
// rowc = {es, e^es, e^{0.2 es}, 0}; evq = {ed, e^ed, e^{0.2 ed}, 0}
template<int F>
__global__ void esed_k(const float* __restrict__ h, const float* __restrict__ asv,
                       const float* __restrict__ adv, float4* __restrict__ rowc,
                       float4* __restrict__ evq) {
    int n = blockIdx.x;
    int t = threadIdx.x;  // 128
    __shared__ float rs[128], rd[128];
    for (int hd = 0; hd < HH; hd++) {
        float vs = 0.f, vd = 0.f;
        for (int f = t; f < F; f += 128) {
            float hv = h[n * (HH * F) + hd * F + f];
            vs = fmaf(hv, asv[hd * F + f], vs);
            vd = fmaf(hv, adv[hd * F + f], vd);
        }
        rs[t] = vs; rd[t] = vd;
        __syncthreads();
#pragma unroll
        for (int s = 64; s > 0; s >>= 1) {
            if (t < s) { rs[t] += rs[t + s]; rd[t] += rd[t + s]; }
            __syncthreads();
        }
        if (t == 0) {
            float es0 = rs[0], ed0 = rd[0];
            rowc[hd * NN + n] = make_float4(es0, expf(es0), expf(0.2f * es0), 0.f);
            evq [hd * NN + n] = make_float4(ed0, expf(ed0), expf(0.2f * ed0), 0.f);
        }
        __syncthreads();
    }
}

// ---------------- fused masked-softmax GAT aggregation, tf32 mma.sync ----------------
// Per (i-tile, head): loop j-tiles; weight phase computes W tile (factorized exp,
// bitmask) into smem as tf32; mma phase does acc += W @ h via m16n8k8 HMMA.
// 256 threads = 8 warps = WM x WN warp grid; warp tile = (IT/WM) x (F/WN).
template<int F, int IT, int WM, int WN>
__global__ void attn_mma_k(const float* __restrict__ h, const float4* __restrict__ rowc,
                           const float4* __restrict__ evq, const unsigned* __restrict__ bits,
                           float* __restrict__ out) {
    constexpr int JT = 64;
    constexpr int HS = F + 8;          // hs row stride (floats): conflict-free B loads
    constexpr int WS = JT + 4;         // ws row stride: conflict-free A loads
    constexpr int MPW = IT / WM;       // rows per warp
    constexpr int MFRAG = MPW / 16;
    constexpr int NPW = F / WN;        // cols per warp
    constexpr int NFRAG = NPW / 8;
    constexpr int JC = (IT * JT) / 256; // weights per thread per tile
    constexpr int TPR = JT / JC;        // weight threads per row
    constexpr int HF = HH * F;
    constexpr int NV = F / 4;          // float4 per h row
    static_assert(WM * WN == 8, "8 warps");
    static_assert(MFRAG >= 1 && NFRAG >= 1, "frag");

    extern __shared__ float smem[];
    float*  hs    = smem;                                   // [JT][HS]
    float*  ws    = hs + JT * HS;                           // [IT][WS]
    float4* evq_s = reinterpret_cast<float4*>(ws + IT * WS);// [JT]
    float*  invd  = reinterpret_cast<float*>(evq_s + JT);   // [IT]
    float*  pd    = invd + IT;                              // [256]

    int t = threadIdx.x;
    int wid = t >> 5, lane = t & 31;
    int gid = lane >> 2, tid4 = lane & 3;
    int head = blockIdx.y;
    int i0 = blockIdx.x * IT;

    // weight-phase mapping (fixed row per thread)
    int wrow = t / TPR;
    int jbase = (t % TPR) * JC;
    float4 rc = rowc[head * NN + i0 + wrow];
    const unsigned* brow = bits + (size_t)(i0 + wrow) * (NN / 32);
    float den = 0.f;

    // mma mapping
    int wm = (wid % WM) * MPW;
    int wn = (wid / WM) * NPW;
    float acc[MFRAG][NFRAG][4];
#pragma unroll
    for (int mf = 0; mf < MFRAG; mf++)
#pragma unroll
        for (int nf = 0; nf < NFRAG; nf++)
#pragma unroll
            for (int c = 0; c < 4; c++) acc[mf][nf][c] = 0.f;

    for (int j0 = 0; j0 < NN; j0 += JT) {
        // ---- stage h tile (raw f32 bits; HMMA reads tf32 subset) + evq ----
#pragma unroll
        for (int idx = t; idx < JT * NV; idx += 256) {
            int jj = idx / NV, fv = idx % NV;
            float4 v = reinterpret_cast<const float4*>(h + (size_t)(j0 + jj) * HF + head * F)[fv];
            *reinterpret_cast<float4*>(&hs[jj * HS + fv * 4]) = v;
        }
        if (t < JT) evq_s[t] = evq[head * NN + j0 + t];
        __syncthreads();

        // ---- weight tile: w = mask * (z>0 ? u*v : p*q), tf32 ----
        unsigned word = brow[(j0 + jbase) >> 5];
        int bit0 = jbase & 31;
#pragma unroll
        for (int q = 0; q < JC; q++) {
            float4 e = evq_s[jbase + q];
            float z = rc.x + e.x;
            bool cpos = z > 0.f;
            float w = (cpos ? rc.y : rc.z) * (cpos ? e.y : e.z);
            if (!((word >> (bit0 + q)) & 1u)) w = 0.f;
            den += w;
            unsigned wt;
            asm("cvt.rna.tf32.f32 %0, %1;" : "=r"(wt) : "f"(w));
            reinterpret_cast<unsigned*>(ws)[wrow * WS + jbase + q] = wt;
        }
        __syncthreads();

        // ---- mma phase: acc += W_tile @ h_tile ----
#pragma unroll
        for (int k = 0; k < JT / 8; k++) {
            unsigned a[MFRAG][4];
#pragma unroll
            for (int mf = 0; mf < MFRAG; mf++) {
                int r0 = wm + mf * 16 + gid;
                const unsigned* wsp = reinterpret_cast<const unsigned*>(ws);
                a[mf][0] = wsp[r0 * WS + k * 8 + tid4];
                a[mf][1] = wsp[(r0 + 8) * WS + k * 8 + tid4];
                a[mf][2] = wsp[r0 * WS + k * 8 + tid4 + 4];
                a[mf][3] = wsp[(r0 + 8) * WS + k * 8 + tid4 + 4];
            }
#pragma unroll
            for (int nf = 0; nf < NFRAG; nf++) {
                unsigned b0 = reinterpret_cast<const unsigned*>(hs)[(k * 8 + tid4) * HS + wn + nf * 8 + gid];
                unsigned b1 = reinterpret_cast<const unsigned*>(hs)[(k * 8 + tid4 + 4) * HS + wn + nf * 8 + gid];
#pragma unroll
                for (int mf = 0; mf < MFRAG; mf++) {
                    asm volatile(
                        "mma.sync.aligned.m16n8k8.row.col.f32.tf32.tf32.f32 "
                        "{%0,%1,%2,%3}, {%4,%5,%6,%7}, {%8,%9}, {%0,%1,%2,%3};"
                        : "+f"(acc[mf][nf][0]), "+f"(acc[mf][nf][1]),
                          "+f"(acc[mf][nf][2]), "+f"(acc[mf][nf][3])
                        : "r"(a[mf][0]), "r"(a[mf][1]), "r"(a[mf][2]), "r"(a[mf][3]),
                          "r"(b0), "r"(b1));
                }
            }
        }
        __syncthreads();
    }

    // ---- denominator reduce ----
    pd[t] = den;
    __syncthreads();
    if (t < IT) {
        float s = 0.f;
#pragma unroll
        for (int k = 0; k < TPR; k++) s += pd[t * TPR + k];
        invd[t] = 1.f / s;
    }
    __syncthreads();

    // ---- epilogue: scale by 1/den, write out ----
#pragma unroll
    for (int mf = 0; mf < MFRAG; mf++) {
        int rb = wm + mf * 16 + gid;
        float iv0 = invd[rb];
        float iv1 = invd[rb + 8];
#pragma unroll
        for (int nf = 0; nf < NFRAG; nf++) {
            int col = head * F + wn + nf * 8 + tid4 * 2;
            float2 v0 = make_float2(acc[mf][nf][0] * iv0, acc[mf][nf][1] * iv0);
            float2 v1 = make_float2(acc[mf][nf][2] * iv1, acc[mf][nf][3] * iv1);
            *reinterpret_cast<float2*>(&out[(size_t)(i0 + rb) * HF + col]) = v0;
            *reinterpret_cast<float2*>(&out[(size_t)(i0 + rb + 8) * HF + col]) = v1;
        }
    }
}

// ---------------- batchnorm stats ----------------
template<int C>
__global__ void bnstats_k(const float* __restrict__ y, float* __restrict__ stats) {
    int c = blockIdx.x;
    int t = threadIdx.x;  // 256
    float s = 0.f, q = 0.f;
    for (int r = t; r < NN; r += 256) {
        float v = y[r * C + c];
        s += v; q = fmaf(v, v, q);
    }
    __shared__ float ss[256], qq[256];
    ss[t] = s; qq[t] = q;
    __syncthreads();
#pragma unroll
    for (int o = 128; o > 0; o >>= 1) {
        if (t < o) { ss[t] += ss[t + o]; qq[t] += qq[t + o]; }
        __syncthreads();
    }
    if (t == 0) {
        float mean = ss[0] / (float)NN;
        float var  = qq[0] / (float)NN - mean * mean;
        stats[c]       = mean;
        stats[128 + c] = rsqrtf(var + 1e-5f);
    }
}

// ---------------- normalize + affine + ELU ----------------
template<int C>
__global__ void bnelu_k(const float* __restrict__ y, const float* __restrict__ stats,
                        const float* __restrict__ g, const float* __restrict__ b,
                        float* __restrict__ out) {
    int idx = blockIdx.x * blockDim.x + threadIdx.x;
    if (idx >= NN * C) return;
    int c = idx % C;
    float v = (y[idx] - stats[c]) * stats[128 + c];
    v = fmaf(v, g[c], b[c]);
    out[idx] = v > 0.f ? v : expm1f(v);
}

// ---------------- launch ----------------
extern "C" void kernel_launch(void* const* d_in, const int* in_sizes, int n_in,
                              void* d_out, int out_size) {
    const float* x   = (const float*)d_in[0];
    const int*   adj = (const int*)d_in[1];
    const float* W1  = (const float*)d_in[2];
    const float* a1s = (const float*)d_in[3];
    const float* a1d = (const float*)d_in[4];
    const float* lw1 = (const float*)d_in[5];
    const float* lb1 = (const float*)d_in[6];
    const float* g1  = (const float*)d_in[7];
    const float* be1 = (const float*)d_in[8];
    const float* W2  = (const float*)d_in[9];
    const float* a2s = (const float*)d_in[10];
    const float* a2d = (const float*)d_in[11];
    const float* lw2 = (const float*)d_in[12];
    const float* lb2 = (const float*)d_in[13];
    const float* g2  = (const float*)d_in[14];
    const float* be2 = (const float*)d_in[15];
    float* out = (float*)d_out;

    float *h1, *x1, *y1, *x2, *h2, *x3, *y2, *stats;
    float4 *rowc1, *evq1, *rowc2, *evq2;
    unsigned* bitsp;
    cudaGetSymbolAddress((void**)&h1,  g_h1);
    cudaGetSymbolAddress((void**)&x1,  g_x1);
    cudaGetSymbolAddress((void**)&y1,  g_y1);
    cudaGetSymbolAddress((void**)&x2,  g_x2);
    cudaGetSymbolAddress((void**)&h2,  g_h2);
    cudaGetSymbolAddress((void**)&x3,  g_x3);
    cudaGetSymbolAddress((void**)&y2,  g_y2);
    cudaGetSymbolAddress((void**)&rowc1, g_rowc1);
    cudaGetSymbolAddress((void**)&evq1,  g_evq1);
    cudaGetSymbolAddress((void**)&rowc2, g_rowc2);
    cudaGetSymbolAddress((void**)&evq2,  g_evq2);
    cudaGetSymbolAddress((void**)&stats, g_stats);
    cudaGetSymbolAddress((void**)&bitsp, g_adjbits);

    // dynamic smem sizes for attn kernels
    const int smem1 = (64 * (128 + 8) + 64 * (64 + 4) + 64 * 4 + 64 + 256) * 4;   // 54528
    const int smem2 = (64 * (32 + 8) + 128 * (64 + 4) + 64 * 4 + 128 + 256) * 4;  // 47616
    cudaFuncSetAttribute(attn_mma_k<128, 64, 2, 4>,
                         cudaFuncAttributeMaxDynamicSharedMemorySize, smem1);
    cudaFuncSetAttribute(attn_mma_k<32, 128, 8, 1>,
                         cudaFuncAttributeMaxDynamicSharedMemorySize, smem2);

    // pack adjacency to bits
    pack_adj_k<<<(NN * NN) / 256, 256>>>(adj, bitsp);

    // ---- layer 1 GAT ----
    gemm_k<64, 64, 16, 4, 4><<<dim3(512 / 64, NN / 64), 256>>>(x, W1, nullptr, h1, NN, 512, 512);
    esed_k<128><<<NN, 128>>>(h1, a1s, a1d, rowc1, evq1);
    attn_mma_k<128, 64, 2, 4><<<dim3(NN / 64, HH), 256, smem1>>>(h1, rowc1, evq1, bitsp, x1);

    // ---- MLP 1 + BN + ELU ----
    gemm_k<64, 64, 16, 4, 4><<<dim3(1, NN / 64), 256>>>(x1, lw1, lb1, y1, NN, 64, 512);
    bnstats_k<64><<<64, 256>>>(y1, stats);
    bnelu_k<64><<<(NN * 64) / 256, 256>>>(y1, stats, g1, be1, x2);

    // ---- layer 2 GAT ----
    gemm_k<64, 64, 16, 4, 4><<<dim3(2, NN / 64), 256>>>(x2, W2, nullptr, h2, NN, 128, 64);
    esed_k<32><<<NN, 128>>>(h2, a2s, a2d, rowc2, evq2);
    attn_mma_k<32, 128, 8, 1><<<dim3(NN / 128, HH), 256, smem2>>>(h2, rowc2, evq2, bitsp, x3);

    // ---- MLP 2 + BN + ELU ----
    gemm_k<64, 16, 16, 4, 1><<<dim3(1, NN / 64), 256>>>(x3, lw2, lb2, y2, NN, 16, 128);
    bnstats_k<16><<<16, 256>>>(y2, stats);
    bnelu_k<16><<<(NN * 16) / 256, 256>>>(y2, stats, g2, be2, out);
}

// round 6
// speedup vs baseline: 1.6806x; 1.0093x over previous
#include <cuda_runtime.h>
#include <cuda_bf16.h>
#include <cstdint>

#define NN 4096
#define HH 4

// ---------------- scratch (device globals; no allocation allowed) ----------------
__device__ float  g_h1 [NN * 512];
__device__ float  g_x1 [NN * 512];
__device__ float  g_y1 [NN * 64];
__device__ float  g_x2 [NN * 64];
__device__ float  g_h2 [NN * 128];
__device__ float  g_x3 [NN * 128];
__device__ float  g_y2 [NN * 16];
__device__ float4 g_rowc1[HH * NN];   // {es, e^es, e^{0.2es}, 0}
__device__ float4 g_evq1 [HH * NN];   // {ed, e^ed, e^{0.2ed}, 0}
__device__ float4 g_rowc2[HH * NN];
__device__ float4 g_evq2 [HH * NN];
__device__ unsigned g_adjbits[NN * (NN / 32)];
__device__ float  g_stats[256];

// ---------------- adjacency packing ----------------
__global__ void pack_adj_k(const int* __restrict__ adj, unsigned* __restrict__ bits) {
    int gid = blockIdx.x * blockDim.x + threadIdx.x;
    unsigned pred = adj[gid] > 0 ? 1u : 0u;
    unsigned word = __ballot_sync(0xffffffffu, pred);
    if ((threadIdx.x & 31) == 0) bits[gid >> 5] = word;
}

// ---------------- generic fp32 tiled GEMM (+optional bias) ----------------
template<int BM, int BN, int BK, int TM, int TN>
__global__ void gemm_k(const float* __restrict__ A, const float* __restrict__ B,
                       const float* __restrict__ bias, float* __restrict__ C,
                       int M, int N, int K) {
    __shared__ float As[BK][BM];
    __shared__ float Bs[BK][BN];
    constexpr int TX = BN / TN;
    int tid = threadIdx.x;
    int tx = tid % TX, ty = tid / TX;
    int m0 = blockIdx.y * BM, n0 = blockIdx.x * BN;
    float acc[TM][TN];
#pragma unroll
    for (int i = 0; i < TM; i++)
#pragma unroll
        for (int j = 0; j < TN; j++) acc[i][j] = 0.f;

    for (int k0 = 0; k0 < K; k0 += BK) {
#pragma unroll
        for (int idx = tid; idx < BM * BK; idx += 256) {
            int m = idx / BK, k = idx % BK;
            As[k][m] = A[(m0 + m) * K + k0 + k];
        }
#pragma unroll
        for (int idx = tid; idx < BK * BN; idx += 256) {
            int k = idx / BN, n = idx % BN;
            Bs[k][n] = B[(k0 + k) * N + n0 + n];
        }
        __syncthreads();
#pragma unroll
        for (int k = 0; k < BK; k++) {
            float ra[TM], rb[TN];
#pragma unroll
            for (int i = 0; i < TM; i++) ra[i] = As[k][ty * TM + i];
#pragma unroll
            for (int j = 0; j < TN; j++) rb[j] = Bs[k][tx * TN + j];
#pragma unroll
            for (int i = 0; i < TM; i++)
#pragma unroll
                for (int j = 0; j < TN; j++) acc[i][j] = fmaf(ra[i], rb[j], acc[i][j]);
        }
        __syncthreads();
    }
#pragma unroll
    for (int i = 0; i < TM; i++)
#pragma unroll
        for (int j = 0; j < TN; j++) {
            float v = acc[i][j];
            if (bias) v += bias[n0 + tx * TN + j];
            C[(m0 + ty * TM + i) * N + n0 + tx * TN + j] = v;
        }
}

// ---------------- per-node logits + factorized exponentials ----------------
template<int F>
__global__ void esed_k(const float* __restrict__ h, const float* __restrict__ asv,
                       const float* __restrict__ adv, float4* __restrict__ rowc,
                       float4* __restrict__ evq) {
    int n = blockIdx.x;
    int t = threadIdx.x;  // 128
    __shared__ float rs[128], rd[128];
    for (int hd = 0; hd < HH; hd++) {
        float vs = 0.f, vd = 0.f;
        for (int f = t; f < F; f += 128) {
            float hv = h[n * (HH * F) + hd * F + f];
            vs = fmaf(hv, asv[hd * F + f], vs);
            vd = fmaf(hv, adv[hd * F + f], vd);
        }
        rs[t] = vs; rd[t] = vd;
        __syncthreads();
#pragma unroll
        for (int s = 64; s > 0; s >>= 1) {
            if (t < s) { rs[t] += rs[t + s]; rd[t] += rd[t + s]; }
            __syncthreads();
        }
        if (t == 0) {
            float es0 = rs[0], ed0 = rd[0];
            rowc[hd * NN + n] = make_float4(es0, expf(es0), expf(0.2f * es0), 0.f);
            evq [hd * NN + n] = make_float4(ed0, expf(ed0), expf(0.2f * ed0), 0.f);
        }
        __syncthreads();
    }
}

// ---------------- fused masked-softmax GAT aggregation, tf32 mma.sync ----------------
// Weights are computed DIRECTLY in the mma A-fragment register layout (no ws
// smem round-trip, single __syncthreads pair per tile). F-dimension can be
// split over blockIdx.z (FE cols per block) for grid scaling.
// 8 warps = WM x WN; warp rows = IT/WM (must be 16), warp cols = FE/WN.
template<int F, int FE, int IT, int WM, int WN>
__global__ void attn_mma_k(const float* __restrict__ h, const float4* __restrict__ rowc,
                           const float4* __restrict__ evq, const unsigned* __restrict__ bits,
                           float* __restrict__ out) {
    constexpr int JT = 64;
    constexpr int HS = FE + 8;          // conflict-free B loads (pad 8 floats)
    constexpr int MPW = IT / WM;
    constexpr int MFRAG = MPW / 16;
    constexpr int NPW = FE / WN;
    constexpr int NFRAG = NPW / 8;
    constexpr int HF = HH * F;
    constexpr int NV = FE / 4;
    static_assert(WM * WN == 8, "8 warps");
    static_assert(MFRAG == 1, "one m-frag per warp");
    static_assert(NFRAG >= 1, "frag");

    __shared__ float    hs[JT * HS];
    __shared__ float4   evq_s[JT];
    __shared__ float4   rowc_s[IT];
    __shared__ unsigned bits_s[IT * 2];   // JT=64 -> 2 words per row
    __shared__ float    dens[IT];

    int t = threadIdx.x;
    int wid = t >> 5, lane = t & 31;
    int gid = lane >> 2, tid4 = lane & 3;
    int head = blockIdx.y;
    int i0 = blockIdx.x * IT;
    int fofs = blockIdx.z * FE;
    int wmi = (wid % WM) * MPW;
    int wni = (wid / WM) * NPW;
    bool cden = (wid / WM) == 0;          // WM warps own den for all IT rows

    int r0 = wmi + gid, r1 = r0 + 8;

    if (t < IT) rowc_s[t] = rowc[head * NN + i0 + t];

    float acc[NFRAG][4];
#pragma unroll
    for (int nf = 0; nf < NFRAG; nf++)
#pragma unroll
        for (int c = 0; c < 4; c++) acc[nf][c] = 0.f;
    float dacc0 = 0.f, dacc1 = 0.f;

    const unsigned* hsu = reinterpret_cast<const unsigned*>(hs);

    for (int j0 = 0; j0 < NN; j0 += JT) {
        // ---- stage h tile (this block's FE cols), evq, adjacency bits ----
#pragma unroll
        for (int idx = t; idx < JT * NV; idx += 256) {
            int jj = idx / NV, fv = idx % NV;
            float4 v = *reinterpret_cast<const float4*>(
                h + (size_t)(j0 + jj) * HF + head * F + fofs + fv * 4);
            *reinterpret_cast<float4*>(&hs[jj * HS + fv * 4]) = v;
        }
        if (t < JT) evq_s[t] = evq[head * NN + j0 + t];
        if (t < IT * 2) bits_s[t] = bits[(size_t)(i0 + t / 2) * (NN / 32) + (j0 >> 5) + (t & 1)];
        __syncthreads();

        float4 rc0 = rowc_s[r0], rc1 = rowc_s[r1];
        unsigned bwa0 = bits_s[r0 * 2], bwa1 = bits_s[r0 * 2 + 1];
        unsigned bwb0 = bits_s[r1 * 2], bwb1 = bits_s[r1 * 2 + 1];

#pragma unroll
        for (int k = 0; k < JT / 8; k++) {
            int c0 = k * 8 + tid4, c1 = c0 + 4;
            float4 e0 = evq_s[c0], e1 = evq_s[c1];
            unsigned wa = (k < 4) ? bwa0 : bwa1;
            unsigned wb = (k < 4) ? bwb0 : bwb1;
            int s0 = c0 & 31, s1 = c1 & 31;

            float z00 = rc0.x + e0.x;
            float w00 = (z00 > 0.f ? rc0.y : rc0.z) * (z00 > 0.f ? e0.y : e0.z);
            if (!((wa >> s0) & 1u)) w00 = 0.f;
            float z10 = rc1.x + e0.x;
            float w10 = (z10 > 0.f ? rc1.y : rc1.z) * (z10 > 0.f ? e0.y : e0.z);
            if (!((wb >> s0) & 1u)) w10 = 0.f;
            float z01 = rc0.x + e1.x;
            float w01 = (z01 > 0.f ? rc0.y : rc0.z) * (z01 > 0.f ? e1.y : e1.z);
            if (!((wa >> s1) & 1u)) w01 = 0.f;
            float z11 = rc1.x + e1.x;
            float w11 = (z11 > 0.f ? rc1.y : rc1.z) * (z11 > 0.f ? e1.y : e1.z);
            if (!((wb >> s1) & 1u)) w11 = 0.f;

            if (cden) { dacc0 += w00 + w01; dacc1 += w10 + w11; }

            unsigned a0, a1, a2, a3;
            asm("cvt.rna.tf32.f32 %0, %1;" : "=r"(a0) : "f"(w00));
            asm("cvt.rna.tf32.f32 %0, %1;" : "=r"(a1) : "f"(w10));
            asm("cvt.rna.tf32.f32 %0, %1;" : "=r"(a2) : "f"(w01));
            asm("cvt.rna.tf32.f32 %0, %1;" : "=r"(a3) : "f"(w11));

#pragma unroll
            for (int nf = 0; nf < NFRAG; nf++) {
                unsigned b0 = hsu[c0 * HS + wni + nf * 8 + gid];
                unsigned b1 = hsu[c1 * HS + wni + nf * 8 + gid];
                asm volatile(
                    "mma.sync.aligned.m16n8k8.row.col.f32.tf32.tf32.f32 "
                    "{%0,%1,%2,%3}, {%4,%5,%6,%7}, {%8,%9}, {%0,%1,%2,%3};"
                    : "+f"(acc[nf][0]), "+f"(acc[nf][1]), "+f"(acc[nf][2]), "+f"(acc[nf][3])
                    : "r"(a0), "r"(a1), "r"(a2), "r"(a3), "r"(b0), "r"(b1));
            }
        }
        __syncthreads();
    }

    // ---- denominator: reduce across the 4 lanes of each quad ----
    dacc0 += __shfl_xor_sync(0xffffffffu, dacc0, 1);
    dacc0 += __shfl_xor_sync(0xffffffffu, dacc0, 2);
    dacc1 += __shfl_xor_sync(0xffffffffu, dacc1, 1);
    dacc1 += __shfl_xor_sync(0xffffffffu, dacc1, 2);
    if (cden && tid4 == 0) { dens[r0] = dacc0; dens[r1] = dacc1; }
    __syncthreads();

    float iv0 = 1.f / dens[r0];
    float iv1 = 1.f / dens[r1];
#pragma unroll
    for (int nf = 0; nf < NFRAG; nf++) {
        int col = head * F + fofs + wni + nf * 8 + tid4 * 2;
        float2 v0 = make_float2(acc[nf][0] * iv0, acc[nf][1] * iv0);
        float2 v1 = make_float2(acc[nf][2] * iv1, acc[nf][3] * iv1);
        *reinterpret_cast<float2*>(&out[(size_t)(i0 + r0) * HF + col]) = v0;
        *reinterpret_cast<float2*>(&out[(size_t)(i0 + r1) * HF + col]) = v1;
    }
}

// ---------------- batchnorm stats ----------------
template<int C>
__global__ void bnstats_k(const float* __restrict__ y, float* __restrict__ stats) {
    int c = blockIdx.x;
    int t = threadIdx.x;  // 256
    float s = 0.f, q = 0.f;
    for (int r = t; r < NN; r += 256) {
        float v = y[r * C + c];
        s += v; q = fmaf(v, v, q);
    }
    __shared__ float ss[256], qq[256];
    ss[t] = s; qq[t] = q;
    __syncthreads();
#pragma unroll
    for (int o = 128; o > 0; o >>= 1) {
        if (t < o) { ss[t] += ss[t + o]; qq[t] += qq[t + o]; }
        __syncthreads();
    }
    if (t == 0) {
        float mean = ss[0] / (float)NN;
        float var  = qq[0] / (float)NN - mean * mean;
        stats[c]       = mean;
        stats[128 + c] = rsqrtf(var + 1e-5f);
    }
}

// ---------------- normalize + affine + ELU ----------------
template<int C>
__global__ void bnelu_k(const float* __restrict__ y, const float* __restrict__ stats,
                        const float* __restrict__ g, const float* __restrict__ b,
                        float* __restrict__ out) {
    int idx = blockIdx.x * blockDim.x + threadIdx.x;
    if (idx >= NN * C) return;
    int c = idx % C;
    float v = (y[idx] - stats[c]) * stats[128 + c];
    v = fmaf(v, g[c], b[c]);
    out[idx] = v > 0.f ? v : expm1f(v);
}

// ---------------- launch ----------------
extern "C" void kernel_launch(void* const* d_in, const int* in_sizes, int n_in,
                              void* d_out, int out_size) {
    const float* x   = (const float*)d_in[0];
    const int*   adj = (const int*)d_in[1];
    const float* W1  = (const float*)d_in[2];
    const float* a1s = (const float*)d_in[3];
    const float* a1d = (const float*)d_in[4];
    const float* lw1 = (const float*)d_in[5];
    const float* lb1 = (const float*)d_in[6];
    const float* g1  = (const float*)d_in[7];
    const float* be1 = (const float*)d_in[8];
    const float* W2  = (const float*)d_in[9];
    const float* a2s = (const float*)d_in[10];
    const float* a2d = (const float*)d_in[11];
    const float* lw2 = (const float*)d_in[12];
    const float* lb2 = (const float*)d_in[13];
    const float* g2  = (const float*)d_in[14];
    const float* be2 = (const float*)d_in[15];
    float* out = (float*)d_out;

    float *h1, *x1, *y1, *x2, *h2, *x3, *y2, *stats;
    float4 *rowc1, *evq1, *rowc2, *evq2;
    unsigned* bitsp;
    cudaGetSymbolAddress((void**)&h1,  g_h1);
    cudaGetSymbolAddress((void**)&x1,  g_x1);
    cudaGetSymbolAddress((void**)&y1,  g_y1);
    cudaGetSymbolAddress((void**)&x2,  g_x2);
    cudaGetSymbolAddress((void**)&h2,  g_h2);
    cudaGetSymbolAddress((void**)&x3,  g_x3);
    cudaGetSymbolAddress((void**)&y2,  g_y2);
    cudaGetSymbolAddress((void**)&rowc1, g_rowc1);
    cudaGetSymbolAddress((void**)&evq1,  g_evq1);
    cudaGetSymbolAddress((void**)&rowc2, g_rowc2);
    cudaGetSymbolAddress((void**)&evq2,  g_evq2);
    cudaGetSymbolAddress((void**)&stats, g_stats);
    cudaGetSymbolAddress((void**)&bitsp, g_adjbits);

    // pack adjacency to bits
    pack_adj_k<<<(NN * NN) / 256, 256>>>(adj, bitsp);

    // ---- layer 1 GAT ----
    gemm_k<128, 64, 16, 8, 4><<<dim3(512 / 64, NN / 128), 256>>>(x, W1, nullptr, h1, NN, 512, 512);
    esed_k<128><<<NN, 128>>>(h1, a1s, a1d, rowc1, evq1);
    // F=128 split into 2 x FE=64; IT=64, WM=4, WN=2 -> grid 64x4x2 = 512 blocks
    attn_mma_k<128, 64, 64, 4, 2><<<dim3(NN / 64, HH, 2), 256>>>(h1, rowc1, evq1, bitsp, x1);

    // ---- MLP 1 + BN + ELU ----
    gemm_k<128, 64, 16, 8, 4><<<dim3(1, NN / 128), 256>>>(x1, lw1, lb1, y1, NN, 64, 512);
    bnstats_k<64><<<64, 256>>>(y1, stats);
    bnelu_k<64><<<(NN * 64) / 256, 256>>>(y1, stats, g1, be1, x2);

    // ---- layer 2 GAT ----
    gemm_k<128, 64, 16, 8, 4><<<dim3(2, NN / 128), 256>>>(x2, W2, nullptr, h2, NN, 128, 64);
    esed_k<32><<<NN, 128>>>(h2, a2s, a2d, rowc2, evq2);
    // F=32, no split; IT=32, WM=2, WN=4 -> grid 128x4 = 512 blocks
    attn_mma_k<32, 32, 32, 2, 4><<<dim3(NN / 32, HH, 1), 256>>>(h2, rowc2, evq2, bitsp, x3);

    // ---- MLP 2 + BN + ELU ----
    gemm_k<64, 16, 16, 4, 1><<<dim3(1, NN / 64), 256>>>(x3, lw2, lb2, y2, NN, 16, 128);
    bnstats_k<16><<<16, 256>>>(y2, stats);
    bnelu_k<16><<<(NN * 16) / 256, 256>>>(y2, stats, g2, be2, out);
}

// round 7
// speedup vs baseline: 2.1976x; 1.3076x over previous
#include <cuda_runtime.h>
#include <cuda_bf16.h>
#include <cstdint>

#define NN 4096
#define HH 4

// ---------------- scratch (device globals; no allocation allowed) ----------------
__device__ float  g_h1 [NN * 512];
__device__ float  g_x1 [NN * 512];
__device__ float  g_y1 [NN * 64];
__device__ float  g_x2 [NN * 64];
__device__ float  g_h2 [NN * 128];
__device__ float  g_x3 [NN * 128];
__device__ float  g_y2 [NN * 16];
__device__ float2 g_rowc1[HH * NN];   // {e^es, e^{0.2es}}
__device__ float2 g_evq1 [HH * NN];   // {e^ed, e^{0.2ed}}
__device__ float2 g_rowc2[HH * NN];
__device__ float2 g_evq2 [HH * NN];
__device__ unsigned g_adjbits[NN * (NN / 32)];
__device__ float  g_stats[256];

// ---------------- cp.async helpers ----------------
__device__ __forceinline__ unsigned smem_u32(const void* p) {
    return (unsigned)__cvta_generic_to_shared(p);
}
#define CP_ASYNC16(dst, src) \
    asm volatile("cp.async.cg.shared.global [%0], [%1], 16;" :: "r"(dst), "l"(src))
#define CP_ASYNC8(dst, src) \
    asm volatile("cp.async.ca.shared.global [%0], [%1], 8;" :: "r"(dst), "l"(src))
#define CP_COMMIT() asm volatile("cp.async.commit_group;")
#define CP_WAIT1()  asm volatile("cp.async.wait_group 1;")
#define CP_WAIT0()  asm volatile("cp.async.wait_group 0;")

// ---------------- adjacency packing ----------------
__global__ void pack_adj_k(const int* __restrict__ adj, unsigned* __restrict__ bits) {
    int gid = blockIdx.x * blockDim.x + threadIdx.x;
    unsigned pred = adj[gid] > 0 ? 1u : 0u;
    unsigned word = __ballot_sync(0xffffffffu, pred);
    if ((threadIdx.x & 31) == 0) bits[gid >> 5] = word;
}

// ---------------- generic fp32 tiled GEMM (+optional bias) ----------------
template<int BM, int BN, int BK, int TM, int TN>
__global__ void gemm_k(const float* __restrict__ A, const float* __restrict__ B,
                       const float* __restrict__ bias, float* __restrict__ C,
                       int M, int N, int K) {
    __shared__ float As[BK][BM];
    __shared__ float Bs[BK][BN];
    constexpr int TX = BN / TN;
    int tid = threadIdx.x;
    int tx = tid % TX, ty = tid / TX;
    int m0 = blockIdx.y * BM, n0 = blockIdx.x * BN;
    float acc[TM][TN];
#pragma unroll
    for (int i = 0; i < TM; i++)
#pragma unroll
        for (int j = 0; j < TN; j++) acc[i][j] = 0.f;

    for (int k0 = 0; k0 < K; k0 += BK) {
#pragma unroll
        for (int idx = tid; idx < BM * BK; idx += 256) {
            int m = idx / BK, k = idx % BK;
            As[k][m] = A[(m0 + m) * K + k0 + k];
        }
#pragma unroll
        for (int idx = tid; idx < BK * BN; idx += 256) {
            int k = idx / BN, n = idx % BN;
            Bs[k][n] = B[(k0 + k) * N + n0 + n];
        }
        __syncthreads();
#pragma unroll
        for (int k = 0; k < BK; k++) {
            float ra[TM], rb[TN];
#pragma unroll
            for (int i = 0; i < TM; i++) ra[i] = As[k][ty * TM + i];
#pragma unroll
            for (int j = 0; j < TN; j++) rb[j] = Bs[k][tx * TN + j];
#pragma unroll
            for (int i = 0; i < TM; i++)
#pragma unroll
                for (int j = 0; j < TN; j++) acc[i][j] = fmaf(ra[i], rb[j], acc[i][j]);
        }
        __syncthreads();
    }
#pragma unroll
    for (int i = 0; i < TM; i++)
#pragma unroll
        for (int j = 0; j < TN; j++) {
            float v = acc[i][j];
            if (bias) v += bias[n0 + tx * TN + j];
            C[(m0 + ty * TM + i) * N + n0 + tx * TN + j] = v;
        }
}

// ---------------- per-node logits -> factorized exponentials ----------------
// rowc = {e^es, e^{0.2 es}}; evq = {e^ed, e^{0.2 ed}}
// (weight later = max(u*v, p*q), exactly exp(leaky_relu(es+ed)))
template<int F>
__global__ void esed_k(const float* __restrict__ h, const float* __restrict__ asv,
                       const float* __restrict__ adv, float2* __restrict__ rowc,
                       float2* __restrict__ evq) {
    int n = blockIdx.x;
    int t = threadIdx.x;  // 128
    __shared__ float rs[128], rd[128];
    for (int hd = 0; hd < HH; hd++) {
        float vs = 0.f, vd = 0.f;
        for (int f = t; f < F; f += 128) {
            float hv = h[n * (HH * F) + hd * F + f];
            vs = fmaf(hv, asv[hd * F + f], vs);
            vd = fmaf(hv, adv[hd * F + f], vd);
        }
        rs[t] = vs; rd[t] = vd;
        __syncthreads();
#pragma unroll
        for (int s = 64; s > 0; s >>= 1) {
            if (t < s) { rs[t] += rs[t + s]; rd[t] += rd[t + s]; }
            __syncthreads();
        }
        if (t == 0) {
            float es0 = rs[0], ed0 = rd[0];
            rowc[hd * NN + n] = make_float2(expf(es0), expf(0.2f * es0));
            evq [hd * NN + n] = make_float2(expf(ed0), expf(0.2f * ed0));
        }
        __syncthreads();
    }
}

// ---------------- fused masked-softmax GAT aggregation, tf32 mma.sync ----------------
// w(i,j) = mask * max(u_i*v_j, p_i*q_j). A-fragments built in registers; h tile
// double-buffered via cp.async. 8 warps = WM x WN; warp = 16 rows x FE/WN cols.
template<int F, int FE, int IT, int WM, int WN>
__global__ __launch_bounds__(256, 3)
void attn_mma_k(const float* __restrict__ h, const float2* __restrict__ rowc,
                const float2* __restrict__ evq, const unsigned* __restrict__ bits,
                float* __restrict__ out) {
    constexpr int JT = 64;
    constexpr int NT = NN / JT;
    constexpr int HS = FE + 8;          // conflict-free B loads
    constexpr int MPW = IT / WM;
    constexpr int NPW = FE / WN;
    constexpr int NFRAG = NPW / 8;
    constexpr int HF = HH * F;
    constexpr int NV = FE / 4;
    static_assert(WM * WN == 8, "8 warps");
    static_assert(MPW == 16, "one m-frag per warp");

    __shared__ float  hs[2][JT * HS];
    __shared__ float2 evq_s[2][JT];
    __shared__ uint2  bits_s[2][IT];
    __shared__ float2 rowc_s[IT];
    __shared__ float  dens[IT];

    int t = threadIdx.x;
    int wid = t >> 5, lane = t & 31;
    int gid = lane >> 2, tid4 = lane & 3;
    int head = blockIdx.y;
    int i0 = blockIdx.x * IT;
    int fofs = blockIdx.z * FE;
    int wmi = (wid % WM) * MPW;
    int wni = (wid / WM) * NPW;
    bool cden = (wid / WM) == 0;

    int r0 = wmi + gid, r1 = r0 + 8;

    if (t < IT) rowc_s[t] = rowc[head * NN + i0 + t];

    const float* hbase = h + head * F + fofs;
    const unsigned* bbase = bits + (size_t)i0 * (NN / 32);

    // tile loader: stage st <- tile j0
    auto load_tile = [&](int st, int j0) {
#pragma unroll
        for (int idx = t; idx < JT * NV; idx += 256) {
            int jj = idx / NV, fv = idx % NV;
            CP_ASYNC16(smem_u32(&hs[st][jj * HS + fv * 4]),
                       hbase + (size_t)(j0 + jj) * HF + fv * 4);
        }
        if (t < JT) CP_ASYNC8(smem_u32(&evq_s[st][t]), evq + head * NN + j0 + t);
        if (t >= 128 && t < 128 + IT)
            CP_ASYNC8(smem_u32(&bits_s[st][t - 128]), bbase + (size_t)(t - 128) * (NN / 32) + (j0 >> 5));
        CP_COMMIT();
    };

    float acc[NFRAG][4];
#pragma unroll
    for (int nf = 0; nf < NFRAG; nf++)
#pragma unroll
        for (int c = 0; c < 4; c++) acc[nf][c] = 0.f;
    float dacc0 = 0.f, dacc1 = 0.f;

    load_tile(0, 0);

    for (int tt = 0; tt < NT; tt++) {
        int st = tt & 1;
        if (tt + 1 < NT) { load_tile(st ^ 1, (tt + 1) * JT); CP_WAIT1(); }
        else             { CP_WAIT0(); }
        __syncthreads();

        float2 rc0 = rowc_s[r0], rc1 = rowc_s[r1];
        uint2 bwa = bits_s[st][r0];
        uint2 bwb = bits_s[st][r1];
        const unsigned* hsu = reinterpret_cast<const unsigned*>(hs[st]);

#pragma unroll
        for (int k = 0; k < JT / 8; k++) {
            int c0 = k * 8 + tid4, c1 = c0 + 4;
            float2 e0 = evq_s[st][c0], e1 = evq_s[st][c1];
            unsigned wa = (k < 4) ? bwa.x : bwa.y;
            unsigned wb = (k < 4) ? bwb.x : bwb.y;
            int s0 = c0 & 31, s1 = c1 & 31;

            float w00 = fmaxf(rc0.x * e0.x, rc0.y * e0.y);
            if (!((wa >> s0) & 1u)) w00 = 0.f;
            float w10 = fmaxf(rc1.x * e0.x, rc1.y * e0.y);
            if (!((wb >> s0) & 1u)) w10 = 0.f;
            float w01 = fmaxf(rc0.x * e1.x, rc0.y * e1.y);
            if (!((wa >> s1) & 1u)) w01 = 0.f;
            float w11 = fmaxf(rc1.x * e1.x, rc1.y * e1.y);
            if (!((wb >> s1) & 1u)) w11 = 0.f;

            if (cden) { dacc0 += w00 + w01; dacc1 += w10 + w11; }

            unsigned a0 = __float_as_uint(w00);
            unsigned a1 = __float_as_uint(w10);
            unsigned a2 = __float_as_uint(w01);
            unsigned a3 = __float_as_uint(w11);

#pragma unroll
            for (int nf = 0; nf < NFRAG; nf++) {
                unsigned b0 = hsu[c0 * HS + wni + nf * 8 + gid];
                unsigned b1 = hsu[c1 * HS + wni + nf * 8 + gid];
                asm volatile(
                    "mma.sync.aligned.m16n8k8.row.col.f32.tf32.tf32.f32 "
                    "{%0,%1,%2,%3}, {%4,%5,%6,%7}, {%8,%9}, {%0,%1,%2,%3};"
                    : "+f"(acc[nf][0]), "+f"(acc[nf][1]), "+f"(acc[nf][2]), "+f"(acc[nf][3])
                    : "r"(a0), "r"(a1), "r"(a2), "r"(a3), "r"(b0), "r"(b1));
            }
        }
        __syncthreads();
    }

    // ---- denominator: quad-lane reduce ----
    dacc0 += __shfl_xor_sync(0xffffffffu, dacc0, 1);
    dacc0 += __shfl_xor_sync(0xffffffffu, dacc0, 2);
    dacc1 += __shfl_xor_sync(0xffffffffu, dacc1, 1);
    dacc1 += __shfl_xor_sync(0xffffffffu, dacc1, 2);
    if (cden && tid4 == 0) { dens[r0] = dacc0; dens[r1] = dacc1; }
    __syncthreads();

    float iv0 = 1.f / dens[r0];
    float iv1 = 1.f / dens[r1];
#pragma unroll
    for (int nf = 0; nf < NFRAG; nf++) {
        int col = head * F + fofs + wni + nf * 8 + tid4 * 2;
        float2 v0 = make_float2(acc[nf][0] * iv0, acc[nf][1] * iv0);
        float2 v1 = make_float2(acc[nf][2] * iv1, acc[nf][3] * iv1);
        *reinterpret_cast<float2*>(&out[(size_t)(i0 + r0) * HF + col]) = v0;
        *reinterpret_cast<float2*>(&out[(size_t)(i0 + r1) * HF + col]) = v1;
    }
}

// ---------------- batchnorm stats ----------------
template<int C>
__global__ void bnstats_k(const float* __restrict__ y, float* __restrict__ stats) {
    int c = blockIdx.x;
    int t = threadIdx.x;  // 256
    float s = 0.f, q = 0.f;
    for (int r = t; r < NN; r += 256) {
        float v = y[r * C + c];
        s += v; q = fmaf(v, v, q);
    }
    __shared__ float ss[256], qq[256];
    ss[t] = s; qq[t] = q;
    __syncthreads();
#pragma unroll
    for (int o = 128; o > 0; o >>= 1) {
        if (t < o) { ss[t] += ss[t + o]; qq[t] += qq[t + o]; }
        __syncthreads();
    }
    if (t == 0) {
        float mean = ss[0] / (float)NN;
        float var  = qq[0] / (float)NN - mean * mean;
        stats[c]       = mean;
        stats[128 + c] = rsqrtf(var + 1e-5f);
    }
}

// ---------------- normalize + affine + ELU ----------------
template<int C>
__global__ void bnelu_k(const float* __restrict__ y, const float* __restrict__ stats,
                        const float* __restrict__ g, const float* __restrict__ b,
                        float* __restrict__ out) {
    int idx = blockIdx.x * blockDim.x + threadIdx.x;
    if (idx >= NN * C) return;
    int c = idx % C;
    float v = (y[idx] - stats[c]) * stats[128 + c];
    v = fmaf(v, g[c], b[c]);
    out[idx] = v > 0.f ? v : expm1f(v);
}

// ---------------- launch ----------------
extern "C" void kernel_launch(void* const* d_in, const int* in_sizes, int n_in,
                              void* d_out, int out_size) {
    const float* x   = (const float*)d_in[0];
    const int*   adj = (const int*)d_in[1];
    const float* W1  = (const float*)d_in[2];
    const float* a1s = (const float*)d_in[3];
    const float* a1d = (const float*)d_in[4];
    const float* lw1 = (const float*)d_in[5];
    const float* lb1 = (const float*)d_in[6];
    const float* g1  = (const float*)d_in[7];
    const float* be1 = (const float*)d_in[8];
    const float* W2  = (const float*)d_in[9];
    const float* a2s = (const float*)d_in[10];
    const float* a2d = (const float*)d_in[11];
    const float* lw2 = (const float*)d_in[12];
    const float* lb2 = (const float*)d_in[13];
    const float* g2  = (const float*)d_in[14];
    const float* be2 = (const float*)d_in[15];
    float* out = (float*)d_out;

    float *h1, *x1, *y1, *x2, *h2, *x3, *y2, *stats;
    float2 *rowc1, *evq1, *rowc2, *evq2;
    unsigned* bitsp;
    cudaGetSymbolAddress((void**)&h1,  g_h1);
    cudaGetSymbolAddress((void**)&x1,  g_x1);
    cudaGetSymbolAddress((void**)&y1,  g_y1);
    cudaGetSymbolAddress((void**)&x2,  g_x2);
    cudaGetSymbolAddress((void**)&h2,  g_h2);
    cudaGetSymbolAddress((void**)&x3,  g_x3);
    cudaGetSymbolAddress((void**)&y2,  g_y2);
    cudaGetSymbolAddress((void**)&rowc1, g_rowc1);
    cudaGetSymbolAddress((void**)&evq1,  g_evq1);
    cudaGetSymbolAddress((void**)&rowc2, g_rowc2);
    cudaGetSymbolAddress((void**)&evq2,  g_evq2);
    cudaGetSymbolAddress((void**)&stats, g_stats);
    cudaGetSymbolAddress((void**)&bitsp, g_adjbits);

    // pack adjacency to bits
    pack_adj_k<<<(NN * NN) / 256, 256>>>(adj, bitsp);

    // ---- layer 1 GAT ----
    gemm_k<128, 64, 16, 8, 4><<<dim3(512 / 64, NN / 128), 256>>>(x, W1, nullptr, h1, NN, 512, 512);
    esed_k<128><<<NN, 128>>>(h1, a1s, a1d, rowc1, evq1);
    // F=128 split into 2 x FE=64; IT=64, WM=4, WN=2 -> 512 blocks
    attn_mma_k<128, 64, 64, 4, 2><<<dim3(NN / 64, HH, 2), 256>>>(h1, rowc1, evq1, bitsp, x1);

    // ---- MLP 1 + BN + ELU ----
    gemm_k<128, 64, 16, 8, 4><<<dim3(1, NN / 128), 256>>>(x1, lw1, lb1, y1, NN, 64, 512);
    bnstats_k<64><<<64, 256>>>(y1, stats);
    bnelu_k<64><<<(NN * 64) / 256, 256>>>(y1, stats, g1, be1, x2);

    // ---- layer 2 GAT ----
    gemm_k<128, 64, 16, 8, 4><<<dim3(2, NN / 128), 256>>>(x2, W2, nullptr, h2, NN, 128, 64);
    esed_k<32><<<NN, 128>>>(h2, a2s, a2d, rowc2, evq2);
    // F=32; IT=32, WM=2, WN=4 -> 512 blocks
    attn_mma_k<32, 32, 32, 2, 4><<<dim3(NN / 32, HH, 1), 256>>>(h2, rowc2, evq2, bitsp, x3);

    // ---- MLP 2 + BN + ELU ----
    gemm_k<64, 16, 16, 4, 1><<<dim3(1, NN / 64), 256>>>(x3, lw2, lb2, y2, NN, 16, 128);
    bnstats_k<16><<<16, 256>>>(y2, stats);
    bnelu_k<16><<<(NN * 16) / 256, 256>>>(y2, stats, g2, be2, out);
}

// round 9
// speedup vs baseline: 3.2034x; 1.4577x over previous
#include <cuda_runtime.h>
#include <cuda_bf16.h>
#include <cstdint>

#define NN 4096
#define HH 4

// ---------------- scratch ----------------
__device__ float  g_h1 [NN * 512];
__device__ float  g_x1 [NN * 512];
__device__ float  g_y1 [NN * 64];
__device__ float  g_x2 [NN * 64];
__device__ float  g_h2 [NN * 128];
__device__ float  g_x3 [NN * 128];
__device__ float  g_y2 [NN * 16];
__device__ float2 g_rowc1[HH * NN];   // {e^es, e^{0.2es}}
__device__ float2 g_evq1 [HH * NN];   // {e^ed, e^{0.2ed}}
__device__ float2 g_rowc2[HH * NN];
__device__ float2 g_evq2 [HH * NN];
__device__ unsigned g_adjbits[NN * (NN / 32)];
__device__ float  g_stats[256];
__device__ float  g_part [2 * NN * 128];   // attn2 partial numerators
__device__ float  g_dpart[2 * HH * NN];    // attn2 partial denominators

// ---------------- helpers ----------------
__device__ __forceinline__ unsigned smem_u32(const void* p) {
    return (unsigned)__cvta_generic_to_shared(p);
}
#define CP_ASYNC16(dst, src) \
    asm volatile("cp.async.cg.shared.global [%0], [%1], 16;" :: "r"(dst), "l"(src))
#define CP_ASYNC8(dst, src) \
    asm volatile("cp.async.ca.shared.global [%0], [%1], 8;" :: "r"(dst), "l"(src))
#define CP_COMMIT() asm volatile("cp.async.commit_group;")
#define CP_WAIT1()  asm volatile("cp.async.wait_group 1;")
#define CP_WAIT0()  asm volatile("cp.async.wait_group 0;")

#define MMA_TF32(acc, a0, a1, a2, a3, b0, b1)                                   \
    asm volatile(                                                               \
        "mma.sync.aligned.m16n8k8.row.col.f32.tf32.tf32.f32 "                   \
        "{%0,%1,%2,%3}, {%4,%5,%6,%7}, {%8,%9}, {%0,%1,%2,%3};"                 \
        : "+f"(acc[0]), "+f"(acc[1]), "+f"(acc[2]), "+f"(acc[3])                \
        : "r"(a0), "r"(a1), "r"(a2), "r"(a3), "r"(b0), "r"(b1))

__device__ __forceinline__ void split_tf32(float v, unsigned& h, unsigned& l) {
    unsigned hv;
    asm("cvt.rna.tf32.f32 %0, %1;" : "=r"(hv) : "f"(v));
    float lo = v - __uint_as_float(hv);
    unsigned lv;
    asm("cvt.rna.tf32.f32 %0, %1;" : "=r"(lv) : "f"(lo));
    h = hv; l = lv;
}

// ---------------- adjacency packing ----------------
__global__ void pack_adj_k(const int* __restrict__ adj, unsigned* __restrict__ bits) {
    int gid = blockIdx.x * blockDim.x + threadIdx.x;
    unsigned pred = adj[gid] > 0 ? 1u : 0u;
    unsigned word = __ballot_sync(0xffffffffu, pred);
    if ((threadIdx.x & 31) == 0) bits[gid >> 5] = word;
}

// ---------------- 3xTF32 MMA GEMM: C = A@B (+bias), fp32-accurate ----------------
__global__ __launch_bounds__(256, 2)
void gemm3t_k(const float* __restrict__ A, const float* __restrict__ B,
              const float* __restrict__ bias, float* __restrict__ C,
              int M, int N, int K) {
    constexpr int BM = 128, BN = 64, BK = 32;
    constexpr int AS = BK + 4;
    constexpr int BS = BN + 4;
    __shared__ unsigned Ah[BM * AS], Al[BM * AS];
    __shared__ unsigned Bh[BK * BS], Bl[BK * BS];

    int t = threadIdx.x;
    int wid = t >> 5, lane = t & 31;
    int gid = lane >> 2, tid4 = lane & 3;
    int m0 = blockIdx.y * BM, n0 = blockIdx.x * BN;
    int wm = (wid & 3) * 32, wn = (wid >> 2) * 32;

    float acc[2][4][4];
#pragma unroll
    for (int mf = 0; mf < 2; mf++)
#pragma unroll
        for (int nf = 0; nf < 4; nf++)
#pragma unroll
            for (int c = 0; c < 4; c++) acc[mf][nf][c] = 0.f;

    for (int k0 = 0; k0 < K; k0 += BK) {
#pragma unroll
        for (int i = 0; i < (BM * BK) / 256; i++) {
            int e = t + i * 256;
            int m = e / BK, k = e % BK;
            unsigned h, l;
            split_tf32(A[(size_t)(m0 + m) * K + k0 + k], h, l);
            Ah[m * AS + k] = h; Al[m * AS + k] = l;
        }
#pragma unroll
        for (int i = 0; i < (BK * BN) / 256; i++) {
            int e = t + i * 256;
            int k = e / BN, n = e % BN;
            unsigned h, l;
            split_tf32(B[(size_t)(k0 + k) * N + n0 + n], h, l);
            Bh[k * BS + n] = h; Bl[k * BS + n] = l;
        }
        __syncthreads();

#pragma unroll
        for (int k8 = 0; k8 < BK / 8; k8++) {
            unsigned ah[2][4], al[2][4];
#pragma unroll
            for (int mf = 0; mf < 2; mf++) {
                int r0 = wm + mf * 16 + gid;
                ah[mf][0] = Ah[r0 * AS + k8 * 8 + tid4];
                ah[mf][1] = Ah[(r0 + 8) * AS + k8 * 8 + tid4];
                ah[mf][2] = Ah[r0 * AS + k8 * 8 + tid4 + 4];
                ah[mf][3] = Ah[(r0 + 8) * AS + k8 * 8 + tid4 + 4];
                al[mf][0] = Al[r0 * AS + k8 * 8 + tid4];
                al[mf][1] = Al[(r0 + 8) * AS + k8 * 8 + tid4];
                al[mf][2] = Al[r0 * AS + k8 * 8 + tid4 + 4];
                al[mf][3] = Al[(r0 + 8) * AS + k8 * 8 + tid4 + 4];
            }
#pragma unroll
            for (int nf = 0; nf < 4; nf++) {
                int cb = wn + nf * 8 + gid;
                unsigned bh0 = Bh[(k8 * 8 + tid4) * BS + cb];
                unsigned bh1 = Bh[(k8 * 8 + tid4 + 4) * BS + cb];
                unsigned bl0 = Bl[(k8 * 8 + tid4) * BS + cb];
                unsigned bl1 = Bl[(k8 * 8 + tid4 + 4) * BS + cb];
#pragma unroll
                for (int mf = 0; mf < 2; mf++) {
                    MMA_TF32(acc[mf][nf], ah[mf][0], ah[mf][1], ah[mf][2], ah[mf][3], bh0, bh1);
                    MMA_TF32(acc[mf][nf], ah[mf][0], ah[mf][1], ah[mf][2], ah[mf][3], bl0, bl1);
                    MMA_TF32(acc[mf][nf], al[mf][0], al[mf][1], al[mf][2], al[mf][3], bh0, bh1);
                }
            }
        }
        __syncthreads();
    }

#pragma unroll
    for (int mf = 0; mf < 2; mf++) {
        int r0 = m0 + wm + mf * 16 + gid;
#pragma unroll
        for (int nf = 0; nf < 4; nf++) {
            int col = n0 + wn + nf * 8 + tid4 * 2;
            float b0 = bias ? bias[col] : 0.f;
            float b1 = bias ? bias[col + 1] : 0.f;
            float2 v0 = make_float2(acc[mf][nf][0] + b0, acc[mf][nf][1] + b1);
            float2 v1 = make_float2(acc[mf][nf][2] + b0, acc[mf][nf][3] + b1);
            *reinterpret_cast<float2*>(&C[(size_t)r0 * N + col]) = v0;
            *reinterpret_cast<float2*>(&C[(size_t)(r0 + 8) * N + col]) = v1;
        }
    }
}

// ---------------- generic fp32 tiled GEMM (small cases) ----------------
template<int BM, int BN, int BK, int TM, int TN>
__global__ void gemm_k(const float* __restrict__ A, const float* __restrict__ B,
                       const float* __restrict__ bias, float* __restrict__ C,
                       int M, int N, int K) {
    __shared__ float As[BK][BM];
    __shared__ float Bs[BK][BN];
    constexpr int TX = BN / TN;
    int tid = threadIdx.x;
    int tx = tid % TX, ty = tid / TX;
    int m0 = blockIdx.y * BM, n0 = blockIdx.x * BN;
    float acc[TM][TN];
#pragma unroll
    for (int i = 0; i < TM; i++)
#pragma unroll
        for (int j = 0; j < TN; j++) acc[i][j] = 0.f;

    for (int k0 = 0; k0 < K; k0 += BK) {
#pragma unroll
        for (int idx = tid; idx < BM * BK; idx += 256) {
            int m = idx / BK, k = idx % BK;
            As[k][m] = A[(m0 + m) * K + k0 + k];
        }
#pragma unroll
        for (int idx = tid; idx < BK * BN; idx += 256) {
            int k = idx / BN, n = idx % BN;
            Bs[k][n] = B[(k0 + k) * N + n0 + n];
        }
        __syncthreads();
#pragma unroll
        for (int k = 0; k < BK; k++) {
            float ra[TM], rb[TN];
#pragma unroll
            for (int i = 0; i < TM; i++) ra[i] = As[k][ty * TM + i];
#pragma unroll
            for (int j = 0; j < TN; j++) rb[j] = Bs[k][tx * TN + j];
#pragma unroll
            for (int i = 0; i < TM; i++)
#pragma unroll
                for (int j = 0; j < TN; j++) acc[i][j] = fmaf(ra[i], rb[j], acc[i][j]);
        }
        __syncthreads();
    }
#pragma unroll
    for (int i = 0; i < TM; i++)
#pragma unroll
        for (int j = 0; j < TN; j++) {
            float v = acc[i][j];
            if (bias) v += bias[n0 + tx * TN + j];
            C[(m0 + ty * TM + i) * N + n0 + tx * TN + j] = v;
        }
}

// ---------------- per-node logits -> factorized exponentials ----------------
template<int F>
__global__ void esed_k(const float* __restrict__ h, const float* __restrict__ asv,
                       const float* __restrict__ adv, float2* __restrict__ rowc,
                       float2* __restrict__ evq) {
    int n = blockIdx.x;
    int t = threadIdx.x;  // 128
    __shared__ float rs[128], rd[128];
    for (int hd = 0; hd < HH; hd++) {
        float vs = 0.f, vd = 0.f;
        for (int f = t; f < F; f += 128) {
            float hv = h[n * (HH * F) + hd * F + f];
            vs = fmaf(hv, asv[hd * F + f], vs);
            vd = fmaf(hv, adv[hd * F + f], vd);
        }
        rs[t] = vs; rd[t] = vd;
        __syncthreads();
#pragma unroll
        for (int s = 64; s > 0; s >>= 1) {
            if (t < s) { rs[t] += rs[t + s]; rd[t] += rd[t + s]; }
            __syncthreads();
        }
        if (t == 0) {
            float es0 = rs[0], ed0 = rd[0];
            rowc[hd * NN + n] = make_float2(expf(es0), expf(0.2f * es0));
            evq [hd * NN + n] = make_float2(expf(ed0), expf(0.2f * ed0));
        }
        __syncthreads();
    }
}

// ---------------- fused masked-softmax GAT aggregation (tf32 mma) ----------------
// WN=1: 8 warps x 16 rows = IT=128 rows; each warp owns all FE cols.
// JSPLIT==1: blockIdx.z splits F; JSPLIT==2: blockIdx.z splits j-range
// (unscaled numerator -> pnum, partial denominator -> pden).
template<int F, int FE, int JSPLIT>
__global__ __launch_bounds__(256, 2)
void attn_mma_k(const float* __restrict__ h, const float2* __restrict__ rowc,
                const float2* __restrict__ evq, const unsigned* __restrict__ bits,
                float* __restrict__ out, float* __restrict__ pnum,
                float* __restrict__ pden) {
    constexpr int IT = 128;
    constexpr int JT = 64;
    constexpr int HS = FE + 8;
    constexpr int NFRAG = FE / 8;
    constexpr int HF = HH * F;
    constexpr int NV = FE / 4;
    constexpr int JSPAN = NN / JSPLIT;
    constexpr int NT = JSPAN / JT;

    __shared__ float  hs[2][JT * HS];
    __shared__ float2 evq_s[2][JT];
    __shared__ uint2  bits_s[2][IT];
    __shared__ float2 rowc_s[IT];
    __shared__ float  dens[IT];

    int t = threadIdx.x;
    int wid = t >> 5, lane = t & 31;
    int gid = lane >> 2, tid4 = lane & 3;
    int head = blockIdx.y;
    int i0 = blockIdx.x * IT;
    int zz = blockIdx.z;
    int fofs = (JSPLIT == 1) ? zz * FE : 0;
    int jbeg = (JSPLIT == 1) ? 0 : zz * JSPAN;

    int r0 = wid * 16 + gid, r1 = r0 + 8;

    if (t < IT) rowc_s[t] = rowc[head * NN + i0 + t];

    const float* hbase = h + head * F + fofs;
    const unsigned* bbase = bits + (size_t)i0 * (NN / 32);

    // one uint2 (2 mask words = JT bits) per row; threads 128..255 cover IT=128 rows
    auto load_tile = [&](int st, int j0) {
#pragma unroll
        for (int idx = t; idx < JT * NV; idx += 256) {
            int jj = idx / NV, fv = idx % NV;
            CP_ASYNC16(smem_u32(&hs[st][jj * HS + fv * 4]),
                       hbase + (size_t)(j0 + jj) * HF + fv * 4);
        }
        if (t < JT) CP_ASYNC8(smem_u32(&evq_s[st][t]), evq + head * NN + j0 + t);
        if (t >= 128) {
            int rr = t - 128;
            CP_ASYNC8(smem_u32(&bits_s[st][rr]), bbase + (size_t)rr * (NN / 32) + (j0 >> 5));
        }
        CP_COMMIT();
    };

    float acc[NFRAG][4];
#pragma unroll
    for (int nf = 0; nf < NFRAG; nf++)
#pragma unroll
        for (int c = 0; c < 4; c++) acc[nf][c] = 0.f;
    float dacc0 = 0.f, dacc1 = 0.f;

    load_tile(0, jbeg);

    for (int tt = 0; tt < NT; tt++) {
        int st = tt & 1;
        if (tt + 1 < NT) { load_tile(st ^ 1, jbeg + (tt + 1) * JT); CP_WAIT1(); }
        else             { CP_WAIT0(); }
        __syncthreads();

        float2 rc0 = rowc_s[r0], rc1 = rowc_s[r1];
        uint2 bwa = bits_s[st][r0];
        uint2 bwb = bits_s[st][r1];
        const unsigned* hsu = reinterpret_cast<const unsigned*>(hs[st]);

#pragma unroll
        for (int k = 0; k < JT / 8; k++) {
            int c0 = k * 8 + tid4, c1 = c0 + 4;
            float2 e0 = evq_s[st][c0], e1 = evq_s[st][c1];
            unsigned wa = (k < 4) ? bwa.x : bwa.y;
            unsigned wb = (k < 4) ? bwb.x : bwb.y;
            int s0 = c0 & 31, s1 = c1 & 31;

            float w00 = fmaxf(rc0.x * e0.x, rc0.y * e0.y);
            if (!((wa >> s0) & 1u)) w00 = 0.f;
            float w10 = fmaxf(rc1.x * e0.x, rc1.y * e0.y);
            if (!((wb >> s0) & 1u)) w10 = 0.f;
            float w01 = fmaxf(rc0.x * e1.x, rc0.y * e1.y);
            if (!((wa >> s1) & 1u)) w01 = 0.f;
            float w11 = fmaxf(rc1.x * e1.x, rc1.y * e1.y);
            if (!((wb >> s1) & 1u)) w11 = 0.f;

            dacc0 += w00 + w01;
            dacc1 += w10 + w11;

            unsigned a0 = __float_as_uint(w00);
            unsigned a1 = __float_as_uint(w10);
            unsigned a2 = __float_as_uint(w01);
            unsigned a3 = __float_as_uint(w11);

#pragma unroll
            for (int nf = 0; nf < NFRAG; nf++) {
                unsigned b0 = hsu[c0 * HS + nf * 8 + gid];
                unsigned b1 = hsu[c1 * HS + nf * 8 + gid];
                MMA_TF32(acc[nf], a0, a1, a2, a3, b0, b1);
            }
        }
        __syncthreads();
    }

    // quad-lane reduce of denominators
    dacc0 += __shfl_xor_sync(0xffffffffu, dacc0, 1);
    dacc0 += __shfl_xor_sync(0xffffffffu, dacc0, 2);
    dacc1 += __shfl_xor_sync(0xffffffffu, dacc1, 1);
    dacc1 += __shfl_xor_sync(0xffffffffu, dacc1, 2);

    if (JSPLIT == 1) {
        if (tid4 == 0) { dens[r0] = dacc0; dens[r1] = dacc1; }
        __syncthreads();
        float iv0 = 1.f / dens[r0];
        float iv1 = 1.f / dens[r1];
#pragma unroll
        for (int nf = 0; nf < NFRAG; nf++) {
            int col = head * F + fofs + nf * 8 + tid4 * 2;
            float2 v0 = make_float2(acc[nf][0] * iv0, acc[nf][1] * iv0);
            float2 v1 = make_float2(acc[nf][2] * iv1, acc[nf][3] * iv1);
            *reinterpret_cast<float2*>(&out[(size_t)(i0 + r0) * HF + col]) = v0;
            *reinterpret_cast<float2*>(&out[(size_t)(i0 + r1) * HF + col]) = v1;
        }
    } else {
        if (tid4 == 0) {
            pden[((size_t)zz * HH + head) * NN + i0 + r0] = dacc0;
            pden[((size_t)zz * HH + head) * NN + i0 + r1] = dacc1;
        }
        float* pb = pnum + (size_t)zz * NN * HF;
#pragma unroll
        for (int nf = 0; nf < NFRAG; nf++) {
            int col = head * F + nf * 8 + tid4 * 2;
            float2 v0 = make_float2(acc[nf][0], acc[nf][1]);
            float2 v1 = make_float2(acc[nf][2], acc[nf][3]);
            *reinterpret_cast<float2*>(&pb[(size_t)(i0 + r0) * HF + col]) = v0;
            *reinterpret_cast<float2*>(&pb[(size_t)(i0 + r1) * HF + col]) = v1;
        }
    }
}

// combine attn2 j-split partials: out = (p0+p1)/(d0+d1)
__global__ void combine2_k(const float* __restrict__ p, const float* __restrict__ dp,
                           float* __restrict__ out) {
    int n = blockIdx.x;
    int t = threadIdx.x;      // 128 = HF for layer 2
    int head = t >> 5;
    float d = dp[head * NN + n] + dp[HH * NN + head * NN + n];
    float v = p[(size_t)n * 128 + t] + p[(size_t)NN * 128 + (size_t)n * 128 + t];
    out[(size_t)n * 128 + t] = v / d;
}

// ---------------- batchnorm stats ----------------
template<int C>
__global__ void bnstats_k(const float* __restrict__ y, float* __restrict__ stats) {
    int c = blockIdx.x;
    int t = threadIdx.x;  // 256
    float s = 0.f, q = 0.f;
    for (int r = t; r < NN; r += 256) {
        float v = y[r * C + c];
        s += v; q = fmaf(v, v, q);
    }
    __shared__ float ss[256], qq[256];
    ss[t] = s; qq[t] = q;
    __syncthreads();
#pragma unroll
    for (int o = 128; o > 0; o >>= 1) {
        if (t < o) { ss[t] += ss[t + o]; qq[t] += qq[t + o]; }
        __syncthreads();
    }
    if (t == 0) {
        float mean = ss[0] / (float)NN;
        float var  = qq[0] / (float)NN - mean * mean;
        stats[c]       = mean;
        stats[128 + c] = rsqrtf(var + 1e-5f);
    }
}

// ---------------- normalize + affine + ELU ----------------
template<int C>
__global__ void bnelu_k(const float* __restrict__ y, const float* __restrict__ stats,
                        const float* __restrict__ g, const float* __restrict__ b,
                        float* __restrict__ out) {
    int idx = blockIdx.x * blockDim.x + threadIdx.x;
    if (idx >= NN * C) return;
    int c = idx % C;
    float v = (y[idx] - stats[c]) * stats[128 + c];
    v = fmaf(v, g[c], b[c]);
    out[idx] = v > 0.f ? v : expm1f(v);
}

// ---------------- launch ----------------
extern "C" void kernel_launch(void* const* d_in, const int* in_sizes, int n_in,
                              void* d_out, int out_size) {
    const float* x   = (const float*)d_in[0];
    const int*   adj = (const int*)d_in[1];
    const float* W1  = (const float*)d_in[2];
    const float* a1s = (const float*)d_in[3];
    const float* a1d = (const float*)d_in[4];
    const float* lw1 = (const float*)d_in[5];
    const float* lb1 = (const float*)d_in[6];
    const float* g1  = (const float*)d_in[7];
    const float* be1 = (const float*)d_in[8];
    const float* W2  = (const float*)d_in[9];
    const float* a2s = (const float*)d_in[10];
    const float* a2d = (const float*)d_in[11];
    const float* lw2 = (const float*)d_in[12];
    const float* lb2 = (const float*)d_in[13];
    const float* g2  = (const float*)d_in[14];
    const float* be2 = (const float*)d_in[15];
    float* out = (float*)d_out;

    float *h1, *x1, *y1, *x2, *h2, *x3, *y2, *stats, *part, *dpart;
    float2 *rowc1, *evq1, *rowc2, *evq2;
    unsigned* bitsp;
    cudaGetSymbolAddress((void**)&h1,  g_h1);
    cudaGetSymbolAddress((void**)&x1,  g_x1);
    cudaGetSymbolAddress((void**)&y1,  g_y1);
    cudaGetSymbolAddress((void**)&x2,  g_x2);
    cudaGetSymbolAddress((void**)&h2,  g_h2);
    cudaGetSymbolAddress((void**)&x3,  g_x3);
    cudaGetSymbolAddress((void**)&y2,  g_y2);
    cudaGetSymbolAddress((void**)&rowc1, g_rowc1);
    cudaGetSymbolAddress((void**)&evq1,  g_evq1);
    cudaGetSymbolAddress((void**)&rowc2, g_rowc2);
    cudaGetSymbolAddress((void**)&evq2,  g_evq2);
    cudaGetSymbolAddress((void**)&stats, g_stats);
    cudaGetSymbolAddress((void**)&part,  g_part);
    cudaGetSymbolAddress((void**)&dpart, g_dpart);
    cudaGetSymbolAddress((void**)&bitsp, g_adjbits);

    // pack adjacency to bits
    pack_adj_k<<<(NN * NN) / 256, 256>>>(adj, bitsp);

    // ---- layer 1 GAT ----
    gemm3t_k<<<dim3(512 / 64, NN / 128), 256>>>(x, W1, nullptr, h1, NN, 512, 512);
    esed_k<128><<<NN, 128>>>(h1, a1s, a1d, rowc1, evq1);
    // F=128, FE=64 (z splits F), IT=128 -> grid 32x4x2 = 256 blocks
    attn_mma_k<128, 64, 1><<<dim3(NN / 128, HH, 2), 256>>>(h1, rowc1, evq1, bitsp, x1, nullptr, nullptr);

    // ---- MLP 1 + BN + ELU ----
    gemm3t_k<<<dim3(1, NN / 128), 256>>>(x1, lw1, lb1, y1, NN, 64, 512);
    bnstats_k<64><<<64, 256>>>(y1, stats);
    bnelu_k<64><<<(NN * 64) / 256, 256>>>(y1, stats, g1, be1, x2);

    // ---- layer 2 GAT ----
    gemm_k<128, 64, 16, 8, 4><<<dim3(2, NN / 128), 256>>>(x2, W2, nullptr, h2, NN, 128, 64);
    esed_k<32><<<NN, 128>>>(h2, a2s, a2d, rowc2, evq2);
    // F=FE=32, j-split x2 -> grid 32x4x2 = 256 blocks, weights computed once
    attn_mma_k<32, 32, 2><<<dim3(NN / 128, HH, 2), 256>>>(h2, rowc2, evq2, bitsp, nullptr, part, dpart);
    combine2_k<<<NN, 128>>>(part, dpart, x3);

    // ---- MLP 2 + BN + ELU ----
    gemm_k<64, 16, 16, 4, 1><<<dim3(1, NN / 64), 256>>>(x3, lw2, lb2, y2, NN, 16, 128);
    bnstats_k<16><<<16, 256>>>(y2, stats);
    bnelu_k<16><<<(NN * 16) / 256, 256>>>(y2, stats, g2, be2, out);
}